// round 15
// baseline (speedup 1.0000x reference)
#include <cuda_runtime.h>
#include <cuda_fp16.h>
#include <cstdint>

#define BB 2
#define SH 2048
#define SE 256
#define SS 2304
#define HH 16
#define DD 128
#define BM 256
#define BN 64
#define NKT (SS/BN)
#define NT 256

// smem (halves): Q 256x144 resident; K 64x144 x2; V 128x80 x2
#define QSTR 144
#define KSTRH 144
#define VSTRH 80
#define QBUFH (256*QSTR)            // 36864
#define KBUFH (64*KSTRH)            // 9216
#define VBUFH (128*VSTRH)           // 10240
#define KBASE QBUFH                 // 36864
#define VBASE (KBASE + 2*KBUFH)     // 55296
#define SMEMH (VBASE + 2*VBUFH)     // 75776 halves
#define SMEM_BYTES (SMEMH*2)        // 151552 B

#define PREP_BLKS ((BB*SS*HH*16)/256)          // 4608 (4 d-pairs per thread)
#define VT_BLKS ((SS/32)*(DD/32)*BB*HH)        // 9216

// Scratch: fp16, RoPE'd, concatenated, head-major, pair-permuted.
static __device__ __half g_Q[(size_t)BB*HH*SS*DD];   // [b,h][s][d']
static __device__ __half g_K[(size_t)BB*HH*SS*DD];   // [b,h][s][d']
static __device__ __half g_Vt[(size_t)BB*HH*SS*DD];  // [b,h][d][s']

__device__ __forceinline__ float ex2(float x) {
    float y; asm("ex2.approx.ftz.f32 %0, %1;" : "=f"(y) : "f"(x)); return y;
}
__device__ __forceinline__ uint32_t f2h2(float lo, float hi) {
    __half2 h = __floats2half2_rn(lo, hi);
    return *(uint32_t*)&h;
}
__device__ __forceinline__ void mma16(float* c, uint32_t a0, uint32_t a1, uint32_t a2,
                                      uint32_t a3, uint32_t b0, uint32_t b1) {
    asm volatile("mma.sync.aligned.m16n8k16.row.col.f32.f16.f16.f32 "
        "{%0,%1,%2,%3}, {%4,%5,%6,%7}, {%8,%9}, {%0,%1,%2,%3};"
        : "+f"(c[0]), "+f"(c[1]), "+f"(c[2]), "+f"(c[3])
        : "r"(a0), "r"(a1), "r"(a2), "r"(a3), "r"(b0), "r"(b1));
}
#define CPA16(dst, src) \
    asm volatile("cp.async.cg.shared.global [%0], [%1], 16;" \
        :: "r"((uint32_t)__cvta_generic_to_shared(dst)), "l"(src))
#define CP_COMMIT() asm volatile("cp.async.commit_group;" ::: "memory")
#define CP_WAIT0()  asm volatile("cp.async.wait_group 0;" ::: "memory")

// ---------------------------------------------------------------------------
// Fused pre-pass (unchanged from round 14).
// ---------------------------------------------------------------------------
__global__ __launch_bounds__(256) void pre_kernel(
        const float* __restrict__ q,  const float* __restrict__ k,
        const float* __restrict__ v,
        const float* __restrict__ eq, const float* __restrict__ ek,
        const float* __restrict__ ev, const float* __restrict__ fr) {
    __shared__ float tile[32][33];
    int bx = blockIdx.x;
    int tid = threadIdx.x;

    if (bx < PREP_BLKS) {
        int idx = bx * 256 + tid;
        int u = idx & 15;
        int G = u >> 1, sg = u & 1;
        int t = idx >> 4;
        int h = t & 15;
        t >>= 4;
        int s = t % SS;
        int b = t / SS;

        int dpA = 8*G + 2*sg;
        int cA = 16*G + 4*sg;

        const float *sq, *sk;
        if (s < SE) {
            size_t off = ((((size_t)b*SE + s)*HH + h)*DD);
            sq = eq + off; sk = ek + off;
        } else {
            size_t off = ((((size_t)b*SH + (s - SE))*HH + h)*DD);
            sq = q + off; sk = k + off;
        }
        float4 qA = *(const float4*)(sq + cA);
        float4 qB = *(const float4*)(sq + cA + 8);
        float4 kA = *(const float4*)(sk + cA);
        float4 kB = *(const float4*)(sk + cA + 8);
        const float4* frp = (const float4*)(fr + ((size_t)s*64 + dpA)*4);
        float4 fA0 = frp[0], fA1 = frp[1];
        float4 fB0 = frp[4], fB1 = frp[5];

        const float qsc = 0.12751744530570984f;  // (1/sqrt(128)) * log2(e)
        size_t rowbase = (((size_t)(b*HH + h))*SS + s)*DD;
        uint32_t* dq = (uint32_t*)(g_Q + rowbase + 16*G + 8*sg);
        uint32_t* dk = (uint32_t*)(g_K + rowbase + 16*G + 8*sg);

        uint4 wq, wk;
        wq.x = f2h2((fA0.x*qA.x + fA0.y*qA.y)*qsc, (fA0.z*qA.x + fA0.w*qA.y)*qsc);
        wq.y = f2h2((fB0.x*qB.x + fB0.y*qB.y)*qsc, (fB0.z*qB.x + fB0.w*qB.y)*qsc);
        wq.z = f2h2((fA1.x*qA.z + fA1.y*qA.w)*qsc, (fA1.z*qA.z + fA1.w*qA.w)*qsc);
        wq.w = f2h2((fB1.x*qB.z + fB1.y*qB.w)*qsc, (fB1.z*qB.z + fB1.w*qB.w)*qsc);
        wk.x = f2h2(fA0.x*kA.x + fA0.y*kA.y, fA0.z*kA.x + fA0.w*kA.y);
        wk.y = f2h2(fB0.x*kB.x + fB0.y*kB.y, fB0.z*kB.x + fB0.w*kB.y);
        wk.z = f2h2(fA1.x*kA.z + fA1.y*kA.w, fA1.z*kA.z + fA1.w*kA.w);
        wk.w = f2h2(fB1.x*kB.z + fB1.y*kB.w, fB1.z*kB.z + fB1.w*kB.w);
        *(uint4*)dq = wq;
        *(uint4*)dk = wk;
    } else {
        int vb = bx - PREP_BLKS;
        int bh = vb / ((SS/32)*(DD/32));
        int rem = vb % ((SS/32)*(DD/32));
        int s0 = (rem % (SS/32)) * 32;
        int d0 = (rem / (SS/32)) * 32;
        int b = bh >> 4, h = bh & 15;
        int tx = tid & 31, ty = tid >> 5;
        #pragma unroll
        for (int j = 0; j < 32; j += 8) {
            int s = s0 + ty + j;
            const float* src;
            if (s < SE) src = ev + (((size_t)b*SE + s)*HH + h)*DD;
            else        src = v + (((size_t)b*SH + (s - SE))*HH + h)*DD;
            tile[ty + j][tx] = src[d0 + tx];
        }
        __syncthreads();
        __half* dst = g_Vt + (size_t)bh*SS*DD;
        int sp = s0 + (tx & 16) + 4*((tx >> 1) & 3) + 2*((tx >> 3) & 1) + (tx & 1);
        #pragma unroll
        for (int j = 0; j < 32; j += 8) {
            int d = d0 + ty + j;
            dst[(size_t)d*SS + sp] = __float2half_rn(tile[tx][ty + j]);
        }
    }
}

// prefetch one BN=64 KV tile (NT=256 threads, 4+4 x16B per thread)
#define PREFETCH_TILE(nkt) do {                                                \
    __half* kb2 = smh + KBASE + ((nkt) & 1)*KBUFH;                             \
    __half* vb2 = smh + VBASE + ((nkt) & 1)*VBUFH;                             \
    const __half* kg2 = Kg + (size_t)(nkt)*BN*DD;                              \
    const __half* vg2 = Vtg + (nkt)*BN;                                        \
    _Pragma("unroll")                                                          \
    for (int it = 0; it < 4; it++) {                                           \
        int i = it*NT + tid;                                                   \
        int r = i >> 4, c = (i & 15) * 8;                                      \
        CPA16(kb2 + r*KSTRH + c, kg2 + r*DD + c);                              \
    }                                                                          \
    _Pragma("unroll")                                                          \
    for (int it = 0; it < 4; it++) {                                           \
        int i = it*NT + tid;                                                   \
        int r = i >> 3, c = (i & 7) * 8;                                       \
        CPA16(vb2 + r*VSTRH + c, vg2 + (size_t)r*SS + c);                      \
    }                                                                          \
    CP_COMMIT();                                                               \
} while (0)

// ---------------------------------------------------------------------------
// Flash attention: 8 warps x 32 q-rows (warp-M=32, BM=256), BN=64.
// Each K/V fragment is loaded ONCE and feeds TWO m16 MMAs -> 0.625x LDS
// traffic per FLOP vs warp-M=16. Q streams from a persistent smem tile.
// ---------------------------------------------------------------------------
__global__ __launch_bounds__(NT, 1) void attn_kernel(float* __restrict__ out) {
    extern __shared__ __half smh[];
    const int tid = threadIdx.x;
    const int w = tid >> 5, lane = tid & 31;
    const int gq = lane >> 2, qq = lane & 3;
    const int qt = blockIdx.x, h = blockIdx.y, b = blockIdx.z;
    const size_t bh = (size_t)(b*HH + h);
    const __half* Kg  = g_K  + bh*SS*DD;
    const __half* Vtg = g_Vt + bh*SS*DD;

    // prologue: Q tile (persistent) + KV tile 0, one commit group
    {
        const __half* Qg = g_Q + bh*SS*DD + (size_t)qt*BM*DD;
        #pragma unroll
        for (int it = 0; it < 16; it++) {
            int i = it*NT + tid;
            int r = i >> 4, c = (i & 15) * 8;
            CPA16(smh + r*QSTR + c, Qg + r*DD + c);
        }
        __half* kb = smh + KBASE;
        __half* vb = smh + VBASE;
        #pragma unroll
        for (int it = 0; it < 4; it++) {
            int i = it*NT + tid;
            int r = i >> 4, c = (i & 15) * 8;
            CPA16(kb + r*KSTRH + c, Kg + r*DD + c);
        }
        #pragma unroll
        for (int it = 0; it < 4; it++) {
            int i = it*NT + tid;
            int r = i >> 3, c = (i & 7) * 8;
            CPA16(vb + r*VSTRH + c, Vtg + (size_t)r*SS + c);
        }
        CP_COMMIT();
    }

    float o0[16][4], o1[16][4];
    #pragma unroll
    for (int j = 0; j < 16; j++)
        #pragma unroll
        for (int e = 0; e < 4; e++) { o0[j][e] = 0.f; o1[j][e] = 0.f; }
    float l00 = 0.f, l01 = 0.f, l10 = 0.f, l11 = 0.f;
    float m00 = -1e9f, m01 = -1e9f, m10 = -1e9f, m11 = -1e9f;

    const __half* qB0 = smh + (w*32 + gq)*QSTR + qq*4;        // block0
    const __half* qB1 = qB0 + 16*QSTR;                        // block1

    for (int kt = 0; kt < NKT; kt++) {
        const __half* kbuf = smh + KBASE + (kt & 1)*KBUFH;
        const __half* vbuf = smh + VBASE + (kt & 1)*VBUFH;

        CP_WAIT0();
        __syncthreads();
        if (kt + 1 < NKT) PREFETCH_TILE(kt + 1);

        // ---- S = Q . K^T : 8 k16-steps x 8 n-tiles, K fragment shared
        //      by both row-blocks ----
        float s0[8][4], s1[8][4];
        #pragma unroll
        for (int j = 0; j < 8; j++)
            #pragma unroll
            for (int e = 0; e < 4; e++) { s0[j][e] = 0.f; s1[j][e] = 0.f; }

        const __half* kB = kbuf + gq*KSTRH + qq*4;
        #pragma unroll
        for (int kg = 0; kg < 8; kg++) {
            uint2 u00 = *(const uint2*)(qB0 + kg*16);
            uint2 u01 = *(const uint2*)(qB0 + 8*QSTR + kg*16);
            uint2 u10 = *(const uint2*)(qB1 + kg*16);
            uint2 u11 = *(const uint2*)(qB1 + 8*QSTR + kg*16);
            #pragma unroll
            for (int j = 0; j < 8; j++) {
                uint2 bb = *(const uint2*)(kB + j*8*KSTRH + kg*16);
                mma16(s0[j], u00.x, u01.x, u00.y, u01.y, bb.x, bb.y);
                mma16(s1[j], u10.x, u11.x, u10.y, u11.y, bb.x, bb.y);
            }
        }

        // ---- online max (4 row-streams), early vote, vote-gated rescale ----
        float t00 = -1e9f, t01 = -1e9f, t10 = -1e9f, t11 = -1e9f;
        #pragma unroll
        for (int j = 0; j < 8; j++) {
            t00 = fmaxf(t00, fmaxf(s0[j][0], s0[j][1]));
            t01 = fmaxf(t01, fmaxf(s0[j][2], s0[j][3]));
            t10 = fmaxf(t10, fmaxf(s1[j][0], s1[j][1]));
            t11 = fmaxf(t11, fmaxf(s1[j][2], s1[j][3]));
        }
        bool grew = (t00 > m00) || (t01 > m01) || (t10 > m10) || (t11 > m11);
        if (__any_sync(0xffffffffu, grew)) {
            t00 = fmaxf(t00, __shfl_xor_sync(0xffffffffu, t00, 1));
            t00 = fmaxf(t00, __shfl_xor_sync(0xffffffffu, t00, 2));
            t01 = fmaxf(t01, __shfl_xor_sync(0xffffffffu, t01, 1));
            t01 = fmaxf(t01, __shfl_xor_sync(0xffffffffu, t01, 2));
            t10 = fmaxf(t10, __shfl_xor_sync(0xffffffffu, t10, 1));
            t10 = fmaxf(t10, __shfl_xor_sync(0xffffffffu, t10, 2));
            t11 = fmaxf(t11, __shfl_xor_sync(0xffffffffu, t11, 1));
            t11 = fmaxf(t11, __shfl_xor_sync(0xffffffffu, t11, 2));
            float n00 = fmaxf(m00, t00), n01 = fmaxf(m01, t01);
            float n10 = fmaxf(m10, t10), n11 = fmaxf(m11, t11);
            float a00 = ex2(m00 - n00), a01 = ex2(m01 - n01);
            float a10 = ex2(m10 - n10), a11 = ex2(m11 - n11);
            m00 = n00; m01 = n01; m10 = n10; m11 = n11;
            l00 *= a00; l01 *= a01; l10 *= a10; l11 *= a11;
            #pragma unroll
            for (int j = 0; j < 16; j++) {
                o0[j][0] *= a00; o0[j][1] *= a00;
                o0[j][2] *= a01; o0[j][3] *= a01;
                o1[j][0] *= a10; o1[j][1] *= a10;
                o1[j][2] *= a11; o1[j][3] *= a11;
            }
        }

        // ---- p = exp2(s - m); P stays in registers as PV A-frags ----
        uint32_t h001[8], h023[8], h101[8], h123[8];
        #pragma unroll
        for (int j = 0; j < 8; j++) {
            float p0 = ex2(s0[j][0] - m00);
            float p1 = ex2(s0[j][1] - m00);
            float p2 = ex2(s0[j][2] - m01);
            float p3 = ex2(s0[j][3] - m01);
            l00 += p0 + p1; l01 += p2 + p3;
            h001[j] = f2h2(p0, p1); h023[j] = f2h2(p2, p3);
            p0 = ex2(s1[j][0] - m10);
            p1 = ex2(s1[j][1] - m10);
            p2 = ex2(s1[j][2] - m11);
            p3 = ex2(s1[j][3] - m11);
            l10 += p0 + p1; l11 += p2 + p3;
            h101[j] = f2h2(p0, p1); h123[j] = f2h2(p2, p3);
        }

        // ---- O += P . V : 4 k16-steps x 16 n-tiles, V fragment shared ----
        const __half* vB = vbuf + gq*VSTRH + qq*4;
        #pragma unroll
        for (int kg = 0; kg < 4; kg++) {
            uint32_t a00 = h001[2*kg],     a01 = h023[2*kg];
            uint32_t a02 = h001[2*kg + 1], a03 = h023[2*kg + 1];
            uint32_t a10 = h101[2*kg],     a11 = h123[2*kg];
            uint32_t a12 = h101[2*kg + 1], a13 = h123[2*kg + 1];
            #pragma unroll
            for (int j = 0; j < 16; j++) {
                uint2 vv = *(const uint2*)(vB + j*8*VSTRH + kg*16);
                mma16(o0[j], a00, a01, a02, a03, vv.x, vv.y);
                mma16(o1[j], a10, a11, a12, a13, vv.x, vv.y);
            }
        }
    }

    // ---- epilogue ----
    l00 += __shfl_xor_sync(0xffffffffu, l00, 1);
    l00 += __shfl_xor_sync(0xffffffffu, l00, 2);
    l01 += __shfl_xor_sync(0xffffffffu, l01, 1);
    l01 += __shfl_xor_sync(0xffffffffu, l01, 2);
    l10 += __shfl_xor_sync(0xffffffffu, l10, 1);
    l10 += __shfl_xor_sync(0xffffffffu, l10, 2);
    l11 += __shfl_xor_sync(0xffffffffu, l11, 1);
    l11 += __shfl_xor_sync(0xffffffffu, l11, 2);
    float i00 = 1.f / l00, i01 = 1.f / l01, i10 = 1.f / l10, i11 = 1.f / l11;

    int r0 = qt*BM + w*32 + gq;
    #pragma unroll
    for (int rb = 0; rb < 4; rb++) {
        int srow = r0 + rb*8;
        float iv = (rb == 0) ? i00 : (rb == 1) ? i01 : (rb == 2) ? i10 : i11;
        float (*oo)[4] = (rb < 2) ? o0 : o1;
        int eo = (rb & 1) ? 2 : 0;
        float* op;
        if (srow < SE) op = out + (size_t)BB*SH*HH*DD + (((size_t)b*SE + srow)*HH + h)*DD;
        else           op = out + (((size_t)b*SH + (srow - SE))*HH + h)*DD;
        #pragma unroll
        for (int j = 0; j < 16; j++) {
            float2 wv;
            wv.x = oo[j][eo]     * iv;
            wv.y = oo[j][eo + 1] * iv;
            *(float2*)(op + j*8 + 2*qq) = wv;
        }
    }
}

// ---------------------------------------------------------------------------
extern "C" void kernel_launch(void* const* d_in, const int* in_sizes, int n_in,
                              void* d_out, int out_size) {
    const float* q  = (const float*)d_in[0];
    const float* k  = (const float*)d_in[1];
    const float* v  = (const float*)d_in[2];
    const float* eq = (const float*)d_in[3];
    const float* ek = (const float*)d_in[4];
    const float* ev = (const float*)d_in[5];
    const float* fr = (const float*)d_in[6];
    float* out = (float*)d_out;

    pre_kernel<<<PREP_BLKS + VT_BLKS, 256>>>(q, k, v, eq, ek, ev, fr);

    static bool attr_set = false;
    if (!attr_set) {
        cudaFuncSetAttribute(attn_kernel,
                             cudaFuncAttributeMaxDynamicSharedMemorySize, SMEM_BYTES);
        attr_set = true;
    }
    dim3 grid(SS / BM, HH, BB);
    attn_kernel<<<grid, NT, SMEM_BYTES>>>(out);
}